// round 12
// baseline (speedup 1.0000x reference)
#include <cuda_runtime.h>

// Problem constants (fixed by the dataset)
#define NN 20000
#define EE 320000
#define DD 128
#define KK 8
#define HH 64
#define KHD 512   // K*H

typedef unsigned long long ull;
// packed fp32x2 helpers (sm_103a; PTX-only forms)
#define DUP2(o, f)  asm("mov.b64 %0, {%1, %1};" : "=l"(o) : "r"(__float_as_uint(f)))
#define FMA2(d, a, b, c) asm("fma.rn.f32x2 %0, %1, %2, %3;" : "=l"(d) : "l"(a), "l"(b), "l"(c))
#define MUL2(d, a, b) asm("mul.rn.f32x2 %0, %1, %2;" : "=l"(d) : "l"(a), "l"(b))

// ---------------- scratch (__device__ globals; no allocations) -------------
// g_cnt and g_denom are zeroed at module load and re-zeroed at the END of
// node_kernel each run, so every graph replay starts from a clean state.
__device__ float g_x[(size_t)EE * DD];      // mean edge features (E,128)
__device__ float g_w[EE * KK];              // exp(leakyrelu(logit))
__device__ float g_er[NN * KK];             // node_feat @ W_r^T
__device__ float g_v[DD * KK];              // W_enc folded with attn_l
__device__ float g_denom[NN * KK];          // softmax denominators
__device__ float g_y[(size_t)NN * KK * DD]; // per-node weighted x sums (N,8,128)
__device__ int   g_cnt[NN];
__device__ int   g_off[NN];
__device__ int   g_cur[NN];
__device__ int   g_perm[EE];

// ---------------- CSR scan -------------------------------------------------
// single-block exclusive scan over 20000 counts (1024 threads x 20 chunk)
__global__ void scan_kernel() {
    __shared__ int s[1024];
    const int CH = 20;
    int tid = threadIdx.x;
    int start = tid * CH;
    int lsum = 0;
    for (int i = 0; i < CH; i++) {
        int idx = start + i;
        if (idx < NN) lsum += g_cnt[idx];
    }
    s[tid] = lsum;
    __syncthreads();
    for (int o = 1; o < 1024; o <<= 1) {
        int v = (tid >= o) ? s[tid - o] : 0;
        __syncthreads();
        s[tid] += v;
        __syncthreads();
    }
    int run = s[tid] - lsum;
    for (int i = 0; i < CH; i++) {
        int idx = start + i;
        if (idx < NN) {
            g_off[idx] = run;
            g_cur[idx] = run;
            run += g_cnt[idx];
        }
    }
}

// ---------------- fused precompute: count + er + v -------------------------
__global__ void er_count_kernel(const float* __restrict__ nf,
                                const float* __restrict__ W_r,
                                const int* __restrict__ dst,
                                const float* __restrict__ W_enc,
                                const float* __restrict__ attn_l) {
    int gtid = blockIdx.x * blockDim.x + threadIdx.x;
    if (gtid < EE) atomicAdd(&g_cnt[dst[gtid]], 1);

    if (blockIdx.x == 0) {
        // 256 threads x 4 entries = 1024 = 128*8 entries of v
        for (int j = 0; j < 4; j++) {
            int i = threadIdx.x * 4 + j;
            int d = i >> 3, k = i & 7;
            float s = 0.f;
            #pragma unroll 8
            for (int h = 0; h < HH; h++)
                s += W_enc[(size_t)d * KHD + k * HH + h] * attn_l[k * HH + h];
            g_v[d * KK + k] = s;
        }
    }

    int w = threadIdx.x >> 5;
    int lane = threadIdx.x & 31;
    int n = blockIdx.x * 8 + w;
    if (n >= NN) return;
    const float* row = nf + (size_t)n * DD;
    float a0 = row[lane], a1 = row[lane + 32], a2 = row[lane + 64], a3 = row[lane + 96];
    #pragma unroll
    for (int k = 0; k < KK; k++) {
        const float* wr = W_r + k * DD;
        float v = a0 * wr[lane] + a1 * wr[lane + 32] + a2 * wr[lane + 64] + a3 * wr[lane + 96];
        #pragma unroll
        for (int o = 16; o > 0; o >>= 1) v += __shfl_xor_sync(0xffffffffu, v, o);
        if (lane == 0) g_er[n * KK + k] = v;
    }
}

// ---------------- edge pass (warp-per-edge, one wave, ldcs, fused fill) ----
// grid = 148 SM x 7 resident blocks = 1036 blocks -> exactly one wave.
#define EDGE_GRID 1036
__global__ __launch_bounds__(128, 7) void edge_kernel(const float4* __restrict__ ef4,
                                                      const int* __restrict__ dst) {
    int lane = threadIdx.x & 31;
    int gw = (blockIdx.x * blockDim.x + threadIdx.x) >> 5;
    int nw = (gridDim.x * blockDim.x) >> 5;

    const float4* gv4 = (const float4*)g_v;
    float4 vv0[4], vv1[4];
    #pragma unroll
    for (int dd = 0; dd < 4; dd++) {
        vv0[dd] = gv4[(4 * lane + dd) * 2 + 0];
        vv1[dd] = gv4[(4 * lane + dd) * 2 + 1];
    }
    int b4 = (lane >> 4) & 1, b3 = (lane >> 3) & 1, b2 = (lane >> 2) & 1;
    int myk = b4 * 4 + b3 * 2 + b2;
    float4* gx4 = (float4*)g_x;
    const float inv3 = 1.0f / 3.0f;

    if (gw >= EE) return;
    const float4* base = ef4 + (size_t)gw * 96;
    float4 c0 = __ldcs(base + lane);
    float4 c1 = __ldcs(base + lane + 32);
    float4 c2 = __ldcs(base + lane + 64);
    int cnd = dst[gw];
    float cer = g_er[cnd * KK + myk];

    for (int e = gw; e < EE; e += nw) {
        int e2 = e + nw;
        int ep = (e2 < EE) ? e2 : e;
        const float4* nbase = ef4 + (size_t)ep * 96;
        float4 n0 = __ldcs(nbase + lane);
        float4 n1 = __ldcs(nbase + lane + 32);
        float4 n2 = __ldcs(nbase + lane + 64);
        int nnd = dst[ep];
        float ner = g_er[nnd * KK + myk];

        // fused CSR fill: one lane per edge claims a slot
        if (lane == 0) {
            int pos = atomicAdd(&g_cur[cnd], 1);
            g_perm[pos] = e;
        }

        float4 x;
        x.x = (c0.x + c1.x + c2.x) * inv3;
        x.y = (c0.y + c1.y + c2.y) * inv3;
        x.z = (c0.z + c1.z + c2.z) * inv3;
        x.w = (c0.w + c1.w + c2.w) * inv3;
        gx4[(size_t)e * 32 + lane] = x;

        float a[8];
        a[0] = x.x * vv0[0].x + x.y * vv0[1].x + x.z * vv0[2].x + x.w * vv0[3].x;
        a[1] = x.x * vv0[0].y + x.y * vv0[1].y + x.z * vv0[2].y + x.w * vv0[3].y;
        a[2] = x.x * vv0[0].z + x.y * vv0[1].z + x.z * vv0[2].z + x.w * vv0[3].z;
        a[3] = x.x * vv0[0].w + x.y * vv0[1].w + x.z * vv0[2].w + x.w * vv0[3].w;
        a[4] = x.x * vv1[0].x + x.y * vv1[1].x + x.z * vv1[2].x + x.w * vv1[3].x;
        a[5] = x.x * vv1[0].y + x.y * vv1[1].y + x.z * vv1[2].y + x.w * vv1[3].y;
        a[6] = x.x * vv1[0].z + x.y * vv1[1].z + x.z * vv1[2].z + x.w * vv1[3].z;
        a[7] = x.x * vv1[0].w + x.y * vv1[1].w + x.z * vv1[2].w + x.w * vv1[3].w;

        #pragma unroll
        for (int j = 0; j < 4; j++) {
            float keep = b4 ? a[j + 4] : a[j];
            float send = b4 ? a[j] : a[j + 4];
            a[j] = keep + __shfl_xor_sync(0xffffffffu, send, 16);
        }
        #pragma unroll
        for (int j = 0; j < 2; j++) {
            float keep = b3 ? a[j + 2] : a[j];
            float send = b3 ? a[j] : a[j + 2];
            a[j] = keep + __shfl_xor_sync(0xffffffffu, send, 8);
        }
        {
            float keep = b2 ? a[1] : a[0];
            float send = b2 ? a[0] : a[1];
            a[0] = keep + __shfl_xor_sync(0xffffffffu, send, 4);
        }
        a[0] += __shfl_xor_sync(0xffffffffu, a[0], 2);
        a[0] += __shfl_xor_sync(0xffffffffu, a[0], 1);

        if ((lane & 3) == 0) {
            float z = a[0] + cer;
            z = (z > 0.f) ? z : 0.01f * z;            // leaky relu
            float wv = __expf(z);                     // shift-free softmax weight
            g_w[e * KK + myk] = wv;
            atomicAdd(&g_denom[cnd * KK + myk], wv);
        }

        c0 = n0; c1 = n1; c2 = n2; cnd = nnd; cer = ner;
    }
}

// ---------------- per-node aggregation (2 warps/node, DIM-split, f32x2) ----
// Block = 256 threads = 8 warps = 4 nodes. Warp h of a node owns dims
// [64h, 64h+64); a lane holds ONE f32x2 -> acc is only 8 ull (16 regs),
// roughly halving register pressure vs the 1-warp version so ~2x more
// warps are resident to cover the scattered x-row latency. Per edge per
// warp: 1 LDG.64 (256B coalesced) + 2 uniform float4 w loads + 8 FMA2.
// NN = 20000 = 5000 blocks x 4 -> no ragged tail, so the __syncthreads
// before the g_cnt/g_denom self-clean is safe.
__global__ __launch_bounds__(256) void node_kernel() {
    int wid = threadIdx.x >> 5;
    int lane = threadIdx.x & 31;
    int m = wid >> 1;               // node slot in block: 0..3
    int h = wid & 1;                // dim half
    int n = blockIdx.x * 4 + m;

    int deg = g_cnt[n];
    int off = g_off[n];
    const ull* gx = (const ull*)g_x;        // x row = 128 floats = 64 ull
    const float4* gw4 = (const float4*)g_w;
    int dix = (h << 5) + lane;              // ull index within row: 0..63

    ull acc[8];
    #pragma unroll
    for (int k = 0; k < 8; k++) acc[k] = 0ull;

    if (deg > 0) {
        int e = g_perm[off];
        ull xd = gx[(size_t)e * 64 + dix];
        float4 wa = gw4[e * 2], wb = gw4[e * 2 + 1];
        for (int i = 0; i < deg; i++) {
            int e2 = (i + 1 < deg) ? g_perm[off + i + 1] : e;
            ull xn = gx[(size_t)e2 * 64 + dix];
            float4 wan = gw4[e2 * 2], wbn = gw4[e2 * 2 + 1];

            ull w2;
            DUP2(w2, wa.x); FMA2(acc[0], xd, w2, acc[0]);
            DUP2(w2, wa.y); FMA2(acc[1], xd, w2, acc[1]);
            DUP2(w2, wa.z); FMA2(acc[2], xd, w2, acc[2]);
            DUP2(w2, wa.w); FMA2(acc[3], xd, w2, acc[3]);
            DUP2(w2, wb.x); FMA2(acc[4], xd, w2, acc[4]);
            DUP2(w2, wb.y); FMA2(acc[5], xd, w2, acc[5]);
            DUP2(w2, wb.z); FMA2(acc[6], xd, w2, acc[6]);
            DUP2(w2, wb.w); FMA2(acc[7], xd, w2, acc[7]);

            xd = xn; wa = wan; wb = wbn;
        }
    }

    // per-head 1/denom (computed redundantly by both warps of the node)
    const float4* dn4 = (const float4*)(g_denom + n * KK);
    float4 d0 = dn4[0], d1 = dn4[1];
    float inv[8];
    inv[0] = (deg > 0) ? __frcp_rn(d0.x) : 0.f;
    inv[1] = (deg > 0) ? __frcp_rn(d0.y) : 0.f;
    inv[2] = (deg > 0) ? __frcp_rn(d0.z) : 0.f;
    inv[3] = (deg > 0) ? __frcp_rn(d0.w) : 0.f;
    inv[4] = (deg > 0) ? __frcp_rn(d1.x) : 0.f;
    inv[5] = (deg > 0) ? __frcp_rn(d1.y) : 0.f;
    inv[6] = (deg > 0) ? __frcp_rn(d1.z) : 0.f;
    inv[7] = (deg > 0) ? __frcp_rn(d1.w) : 0.f;

    // y layout (n,k,d): per k, this warp's 64 dims = ull indices k*64 + dix
    ull* gy = (ull*)g_y;                    // node = 1024 floats = 512 ull
    #pragma unroll
    for (int k = 0; k < 8; k++) {
        ull iv, o;
        DUP2(iv, inv[k]);
        MUL2(o, acc[k], iv);
        gy[(size_t)n * 512 + (size_t)k * 64 + dix] = o;
    }

    __syncthreads();   // both warps of every node finished reading cnt/denom
    if (h == 0 && lane == 0) g_cnt[n] = 0;
    if (h == 0 && lane < KK) g_denom[n * KK + lane] = 0.f;
}

// ---------------- block-diagonal GEMM with packed f32x2 FMA ----------------
// out[n,k,:] = y[n,k,:] @ W_k.  Tile 128(n) x 64(h), BK=32, thread 8x4.
__global__ __launch_bounds__(256) void out_kernel(const float* __restrict__ W_enc,
                                                  float* __restrict__ out) {
    __shared__ float As[32][130];   // [d][row], 130 pad: 8B-aligned rows
    __shared__ float Ws[32][65];
    int k = blockIdx.y;
    int n0 = blockIdx.x * 128;
    int tid = threadIdx.x;
    int tx = tid & 15, ty = tid >> 4;
    int ty8 = ty * 8, tx4 = tx * 4;

    ull c[4][4];                    // [row-pair][cc], each holds rows (2j, 2j+1)
    #pragma unroll
    for (int j = 0; j < 4; j++)
        #pragma unroll
        for (int cc = 0; cc < 4; cc++) c[j][cc] = 0ull;

    for (int kk = 0; kk < DD; kk += 32) {
        #pragma unroll
        for (int p = 0; p < 16; p++) {
            int q = tid + 256 * p;
            int row = q >> 5, d = q & 31;
            int n = n0 + row;
            As[d][row] = (n < NN) ? g_y[(size_t)n * (KK * DD) + k * DD + kk + d] : 0.f;
        }
        #pragma unroll
        for (int p = 0; p < 8; p++) {
            int q = tid + 256 * p;
            int d = q >> 6, h = q & 63;
            Ws[d][h] = W_enc[(size_t)(kk + d) * KHD + k * HH + h];
        }
        __syncthreads();
        #pragma unroll
        for (int d = 0; d < 32; d++) {
            ull a[4];
            a[0] = *(const ull*)&As[d][ty8];
            a[1] = *(const ull*)&As[d][ty8 + 2];
            a[2] = *(const ull*)&As[d][ty8 + 4];
            a[3] = *(const ull*)&As[d][ty8 + 6];
            #pragma unroll
            for (int cc = 0; cc < 4; cc++) {
                ull bb;
                DUP2(bb, Ws[d][tx4 + cc]);
                FMA2(c[0][cc], a[0], bb, c[0][cc]);
                FMA2(c[1][cc], a[1], bb, c[1][cc]);
                FMA2(c[2][cc], a[2], bb, c[2][cc]);
                FMA2(c[3][cc], a[3], bb, c[3][cc]);
            }
        }
        __syncthreads();
    }
    #pragma unroll
    for (int j = 0; j < 4; j++) {
        int r0 = n0 + ty8 + 2 * j;
        #pragma unroll
        for (int cc = 0; cc < 4; cc++) {
            unsigned int lo, hi;
            asm("mov.b64 {%0, %1}, %2;" : "=r"(lo), "=r"(hi) : "l"(c[j][cc]));
            if (r0 < NN)
                out[(size_t)r0 * KHD + k * HH + tx4 + cc] = __uint_as_float(lo);
            if (r0 + 1 < NN)
                out[(size_t)(r0 + 1) * KHD + k * HH + tx4 + cc] = __uint_as_float(hi);
        }
    }
}

// ---------------- launch ----------------------------------------------------
// node_kernel sits at my launch index 3 -> IT is the profiled kernel.
extern "C" void kernel_launch(void* const* d_in, const int* in_sizes, int n_in,
                              void* d_out, int out_size) {
    const float* node_feat = (const float*)d_in[0]; // (N,128)
    const float* edge_feat = (const float*)d_in[1]; // (E,3,128)
    const float* W_enc     = (const float*)d_in[2]; // (128,512)
    const float* attn_l    = (const float*)d_in[3]; // (1,8,64)
    const float* W_r       = (const float*)d_in[4]; // (8,128)
    const int*   dst       = (const int*)d_in[5];   // (E,)
    float* out = (float*)d_out;                     // (N,8,64)

    er_count_kernel<<<(NN + 7) / 8, 256>>>(node_feat, W_r, dst, W_enc, attn_l); // 0
    scan_kernel<<<1, 1024>>>();                                                 // 1
    edge_kernel<<<EDGE_GRID, 128>>>((const float4*)edge_feat, dst);             // 2
    node_kernel<<<NN / 4, 256>>>();                                             // 3  <- profiled
    out_kernel<<<dim3((NN + 127) / 128, 8), 256>>>(W_enc, out);                 // 4
}

// round 13
// speedup vs baseline: 1.2008x; 1.2008x over previous
#include <cuda_runtime.h>

// Problem constants (fixed by the dataset)
#define NN 20000
#define EE 320000
#define DD 128
#define KK 8
#define HH 64
#define KHD 512   // K*H

typedef unsigned long long ull;
// packed fp32x2 helpers (sm_103a; PTX-only forms)
#define DUP2(o, f)  asm("mov.b64 %0, {%1, %1};" : "=l"(o) : "r"(__float_as_uint(f)))
#define FMA2(d, a, b, c) asm("fma.rn.f32x2 %0, %1, %2, %3;" : "=l"(d) : "l"(a), "l"(b), "l"(c))
#define MUL2(d, a, b) asm("mul.rn.f32x2 %0, %1, %2;" : "=l"(d) : "l"(a), "l"(b))
// cp.async helpers
#define CP_ASYNC16(s, g) asm volatile("cp.async.cg.shared.global [%0], [%1], 16;" :: "r"(s), "l"(g) : "memory")
#define CP_COMMIT()      asm volatile("cp.async.commit_group;" ::: "memory")
#define CP_WAIT0()       asm volatile("cp.async.wait_group 0;" ::: "memory")
#define CP_WAIT1()       asm volatile("cp.async.wait_group 1;" ::: "memory")

static __device__ __forceinline__ unsigned sm32(const void* p) {
    return (unsigned)__cvta_generic_to_shared(p);
}

// ---------------- scratch (__device__ globals; no allocations) -------------
// g_cnt and g_denom are zeroed at module load and re-zeroed at the END of
// node_kernel each run, so every graph replay starts from a clean state.
__device__ float g_x[(size_t)EE * DD];      // mean edge features (E,128)
__device__ float g_w[EE * KK];              // exp(leakyrelu(logit))
__device__ float g_er[NN * KK];             // node_feat @ W_r^T
__device__ float g_v[DD * KK];              // W_enc folded with attn_l
__device__ float g_denom[NN * KK];          // softmax denominators
__device__ float g_y[(size_t)NN * KK * DD]; // per-node weighted x sums (N,8,128)
__device__ int   g_cnt[NN];
__device__ int   g_off[NN];
__device__ int   g_cur[NN];
__device__ int   g_perm[EE];

// ---------------- CSR scan -------------------------------------------------
__global__ void scan_kernel() {
    __shared__ int s[1024];
    const int CH = 20;
    int tid = threadIdx.x;
    int start = tid * CH;
    int lsum = 0;
    for (int i = 0; i < CH; i++) {
        int idx = start + i;
        if (idx < NN) lsum += g_cnt[idx];
    }
    s[tid] = lsum;
    __syncthreads();
    for (int o = 1; o < 1024; o <<= 1) {
        int v = (tid >= o) ? s[tid - o] : 0;
        __syncthreads();
        s[tid] += v;
        __syncthreads();
    }
    int run = s[tid] - lsum;
    for (int i = 0; i < CH; i++) {
        int idx = start + i;
        if (idx < NN) {
            g_off[idx] = run;
            g_cur[idx] = run;
            run += g_cnt[idx];
        }
    }
}

// ---------------- fused precompute: count + er + v -------------------------
__global__ void er_count_kernel(const float* __restrict__ nf,
                                const float* __restrict__ W_r,
                                const int* __restrict__ dst,
                                const float* __restrict__ W_enc,
                                const float* __restrict__ attn_l) {
    int gtid = blockIdx.x * blockDim.x + threadIdx.x;
    if (gtid < EE) atomicAdd(&g_cnt[dst[gtid]], 1);

    if (blockIdx.x == 0) {
        for (int j = 0; j < 4; j++) {
            int i = threadIdx.x * 4 + j;
            int d = i >> 3, k = i & 7;
            float s = 0.f;
            #pragma unroll 8
            for (int h = 0; h < HH; h++)
                s += W_enc[(size_t)d * KHD + k * HH + h] * attn_l[k * HH + h];
            g_v[d * KK + k] = s;
        }
    }

    int w = threadIdx.x >> 5;
    int lane = threadIdx.x & 31;
    int n = blockIdx.x * 8 + w;
    if (n >= NN) return;
    const float* row = nf + (size_t)n * DD;
    float a0 = row[lane], a1 = row[lane + 32], a2 = row[lane + 64], a3 = row[lane + 96];
    #pragma unroll
    for (int k = 0; k < KK; k++) {
        const float* wr = W_r + k * DD;
        float v = a0 * wr[lane] + a1 * wr[lane + 32] + a2 * wr[lane + 64] + a3 * wr[lane + 96];
        #pragma unroll
        for (int o = 16; o > 0; o >>= 1) v += __shfl_xor_sync(0xffffffffu, v, o);
        if (lane == 0) g_er[n * KK + k] = v;
    }
}

// ---------------- edge pass (warp-per-edge, one wave, ldcs, fused fill) ----
#define EDGE_GRID 1036
__global__ __launch_bounds__(128, 7) void edge_kernel(const float4* __restrict__ ef4,
                                                      const int* __restrict__ dst) {
    int lane = threadIdx.x & 31;
    int gw = (blockIdx.x * blockDim.x + threadIdx.x) >> 5;
    int nw = (gridDim.x * blockDim.x) >> 5;

    const float4* gv4 = (const float4*)g_v;
    float4 vv0[4], vv1[4];
    #pragma unroll
    for (int dd = 0; dd < 4; dd++) {
        vv0[dd] = gv4[(4 * lane + dd) * 2 + 0];
        vv1[dd] = gv4[(4 * lane + dd) * 2 + 1];
    }
    int b4 = (lane >> 4) & 1, b3 = (lane >> 3) & 1, b2 = (lane >> 2) & 1;
    int myk = b4 * 4 + b3 * 2 + b2;
    float4* gx4 = (float4*)g_x;
    const float inv3 = 1.0f / 3.0f;

    if (gw >= EE) return;
    const float4* base = ef4 + (size_t)gw * 96;
    float4 c0 = __ldcs(base + lane);
    float4 c1 = __ldcs(base + lane + 32);
    float4 c2 = __ldcs(base + lane + 64);
    int cnd = dst[gw];
    float cer = g_er[cnd * KK + myk];

    for (int e = gw; e < EE; e += nw) {
        int e2 = e + nw;
        int ep = (e2 < EE) ? e2 : e;
        const float4* nbase = ef4 + (size_t)ep * 96;
        float4 n0 = __ldcs(nbase + lane);
        float4 n1 = __ldcs(nbase + lane + 32);
        float4 n2 = __ldcs(nbase + lane + 64);
        int nnd = dst[ep];
        float ner = g_er[nnd * KK + myk];

        // fused CSR fill: one lane per edge claims a slot
        if (lane == 0) {
            int pos = atomicAdd(&g_cur[cnd], 1);
            g_perm[pos] = e;
        }

        float4 x;
        x.x = (c0.x + c1.x + c2.x) * inv3;
        x.y = (c0.y + c1.y + c2.y) * inv3;
        x.z = (c0.z + c1.z + c2.z) * inv3;
        x.w = (c0.w + c1.w + c2.w) * inv3;
        gx4[(size_t)e * 32 + lane] = x;

        float a[8];
        a[0] = x.x * vv0[0].x + x.y * vv0[1].x + x.z * vv0[2].x + x.w * vv0[3].x;
        a[1] = x.x * vv0[0].y + x.y * vv0[1].y + x.z * vv0[2].y + x.w * vv0[3].y;
        a[2] = x.x * vv0[0].z + x.y * vv0[1].z + x.z * vv0[2].z + x.w * vv0[3].z;
        a[3] = x.x * vv0[0].w + x.y * vv0[1].w + x.z * vv0[2].w + x.w * vv0[3].w;
        a[4] = x.x * vv1[0].x + x.y * vv1[1].x + x.z * vv1[2].x + x.w * vv1[3].x;
        a[5] = x.x * vv1[0].y + x.y * vv1[1].y + x.z * vv1[2].y + x.w * vv1[3].y;
        a[6] = x.x * vv1[0].z + x.y * vv1[1].z + x.z * vv1[2].z + x.w * vv1[3].z;
        a[7] = x.x * vv1[0].w + x.y * vv1[1].w + x.z * vv1[2].w + x.w * vv1[3].w;

        #pragma unroll
        for (int j = 0; j < 4; j++) {
            float keep = b4 ? a[j + 4] : a[j];
            float send = b4 ? a[j] : a[j + 4];
            a[j] = keep + __shfl_xor_sync(0xffffffffu, send, 16);
        }
        #pragma unroll
        for (int j = 0; j < 2; j++) {
            float keep = b3 ? a[j + 2] : a[j];
            float send = b3 ? a[j] : a[j + 2];
            a[j] = keep + __shfl_xor_sync(0xffffffffu, send, 8);
        }
        {
            float keep = b2 ? a[1] : a[0];
            float send = b2 ? a[0] : a[1];
            a[0] = keep + __shfl_xor_sync(0xffffffffu, send, 4);
        }
        a[0] += __shfl_xor_sync(0xffffffffu, a[0], 2);
        a[0] += __shfl_xor_sync(0xffffffffu, a[0], 1);

        if ((lane & 3) == 0) {
            float z = a[0] + cer;
            z = (z > 0.f) ? z : 0.01f * z;            // leaky relu
            float wv = __expf(z);                     // shift-free softmax weight
            g_w[e * KK + myk] = wv;
            atomicAdd(&g_denom[cnd * KK + myk], wv);
        }

        c0 = n0; c1 = n1; c2 = n2; cnd = nnd; cer = ner;
    }
}

// ---------------- per-node aggregation: warp-per-node + cp.async batches ---
// One warp per node (R11 topology, proven best). x rows + w rows staged into
// smem in 8-edge batches via cp.async, double-buffered: ~4KB in flight per
// warp at ZERO register cost -> MLP no longer capped by the register file.
// Indices: one coalesced perm load per batch, broadcast via shfl (removes
// the perm->x dependent chain). Consumption: lane reads back exactly the
// 16B x-chunk it issued (no cross-lane hazard); w is cross-lane, guarded by
// __syncwarp. Block = 128 thr = 4 warps = 4 nodes; 34KB static smem ->
// 6 blocks/SM = 24 warps with ~96KB of loads in flight per SM.
__global__ __launch_bounds__(128) void node_kernel() {
    __shared__ __align__(16) float xbuf[4][2][8][128];  // 32 KB
    __shared__ __align__(16) float wbuf[4][2][8][8];    //  2 KB
    int wid = threadIdx.x >> 5;
    int lane = threadIdx.x & 31;
    int n = blockIdx.x * 4 + wid;

    int deg = g_cnt[n];
    int off = g_off[n];
    int nb = (deg + 7) >> 3;

    ull acc[8][2];
    #pragma unroll
    for (int k = 0; k < 8; k++) { acc[k][0] = 0ull; acc[k][1] = 0ull; }

    if (deg > 0) {
        // ---- batch issue (macro-ish lambda) ----
        auto issue = [&](int b, int buf) {
            int base = b * 8;
            int cnt = deg - base; if (cnt > 8) cnt = 8;
            int pe = g_perm[off + base + min(lane & 7, cnt - 1)];
            int ej[8];
            #pragma unroll
            for (int j = 0; j < 8; j++) {
                int jj = (j < cnt) ? j : (cnt - 1);
                ej[j] = __shfl_sync(0xffffffffu, pe, jj);
            }
            #pragma unroll
            for (int j = 0; j < 8; j++) {
                unsigned s = sm32(&xbuf[wid][buf][j][lane * 4]);
                const float* g = g_x + (size_t)ej[j] * DD + lane * 4;
                CP_ASYNC16(s, g);
            }
            if (lane < 16) {
                int j = lane >> 1;
                unsigned s = sm32(&wbuf[wid][buf][j][(lane & 1) * 4]);
                const float* g = g_w + (size_t)ej[j] * KK + (lane & 1) * 4;
                CP_ASYNC16(s, g);
            }
            CP_COMMIT();
        };

        issue(0, 0);
        if (nb > 1) issue(1, 1);

        for (int b = 0; b < nb; b++) {
            if (b + 1 < nb) { CP_WAIT1(); } else { CP_WAIT0(); }
            __syncwarp();
            int buf = b & 1;
            int base = b * 8;
            int cnt = deg - base; if (cnt > 8) cnt = 8;
            for (int j = 0; j < cnt; j++) {
                const float4* wrow = (const float4*)&wbuf[wid][buf][j][0];
                float4 wa = wrow[0], wb = wrow[1];
                ulonglong2 xd = *(const ulonglong2*)&xbuf[wid][buf][j][lane * 4];
                ull w2;
                DUP2(w2, wa.x); FMA2(acc[0][0], xd.x, w2, acc[0][0]); FMA2(acc[0][1], xd.y, w2, acc[0][1]);
                DUP2(w2, wa.y); FMA2(acc[1][0], xd.x, w2, acc[1][0]); FMA2(acc[1][1], xd.y, w2, acc[1][1]);
                DUP2(w2, wa.z); FMA2(acc[2][0], xd.x, w2, acc[2][0]); FMA2(acc[2][1], xd.y, w2, acc[2][1]);
                DUP2(w2, wa.w); FMA2(acc[3][0], xd.x, w2, acc[3][0]); FMA2(acc[3][1], xd.y, w2, acc[3][1]);
                DUP2(w2, wb.x); FMA2(acc[4][0], xd.x, w2, acc[4][0]); FMA2(acc[4][1], xd.y, w2, acc[4][1]);
                DUP2(w2, wb.y); FMA2(acc[5][0], xd.x, w2, acc[5][0]); FMA2(acc[5][1], xd.y, w2, acc[5][1]);
                DUP2(w2, wb.z); FMA2(acc[6][0], xd.x, w2, acc[6][0]); FMA2(acc[6][1], xd.y, w2, acc[6][1]);
                DUP2(w2, wb.w); FMA2(acc[7][0], xd.x, w2, acc[7][0]); FMA2(acc[7][1], xd.y, w2, acc[7][1]);
            }
            if (b + 2 < nb) {
                __syncwarp();            // all lanes done reading this buffer
                issue(b + 2, buf);
            }
        }
    }

    // per-head 1/denom, applied once (packed multiply)
    const float4* dn4 = (const float4*)(g_denom + n * KK);
    float4 d0 = dn4[0], d1 = dn4[1];
    float inv[8];
    inv[0] = (deg > 0) ? __frcp_rn(d0.x) : 0.f;
    inv[1] = (deg > 0) ? __frcp_rn(d0.y) : 0.f;
    inv[2] = (deg > 0) ? __frcp_rn(d0.z) : 0.f;
    inv[3] = (deg > 0) ? __frcp_rn(d0.w) : 0.f;
    inv[4] = (deg > 0) ? __frcp_rn(d1.x) : 0.f;
    inv[5] = (deg > 0) ? __frcp_rn(d1.y) : 0.f;
    inv[6] = (deg > 0) ? __frcp_rn(d1.z) : 0.f;
    inv[7] = (deg > 0) ? __frcp_rn(d1.w) : 0.f;

    ulonglong2* gy2 = (ulonglong2*)g_y;
    #pragma unroll
    for (int k = 0; k < 8; k++) {
        ull iv;
        DUP2(iv, inv[k]);
        ulonglong2 o;
        MUL2(o.x, acc[k][0], iv);
        MUL2(o.y, acc[k][1], iv);
        gy2[(size_t)n * 256 + k * 32 + lane] = o;
    }

    __syncwarp();   // this node's warp finished reading g_cnt/g_denom
    if (lane == 0) g_cnt[n] = 0;
    if (lane < KK) g_denom[n * KK + lane] = 0.f;
}

// ---------------- block-diagonal GEMM with packed f32x2 FMA ----------------
__global__ __launch_bounds__(256) void out_kernel(const float* __restrict__ W_enc,
                                                  float* __restrict__ out) {
    __shared__ float As[32][130];   // [d][row], 130 pad: 8B-aligned rows
    __shared__ float Ws[32][65];
    int k = blockIdx.y;
    int n0 = blockIdx.x * 128;
    int tid = threadIdx.x;
    int tx = tid & 15, ty = tid >> 4;
    int ty8 = ty * 8, tx4 = tx * 4;

    ull c[4][4];
    #pragma unroll
    for (int j = 0; j < 4; j++)
        #pragma unroll
        for (int cc = 0; cc < 4; cc++) c[j][cc] = 0ull;

    for (int kk = 0; kk < DD; kk += 32) {
        #pragma unroll
        for (int p = 0; p < 16; p++) {
            int q = tid + 256 * p;
            int row = q >> 5, d = q & 31;
            int n = n0 + row;
            As[d][row] = (n < NN) ? g_y[(size_t)n * (KK * DD) + k * DD + kk + d] : 0.f;
        }
        #pragma unroll
        for (int p = 0; p < 8; p++) {
            int q = tid + 256 * p;
            int d = q >> 6, h = q & 63;
            Ws[d][h] = W_enc[(size_t)(kk + d) * KHD + k * HH + h];
        }
        __syncthreads();
        #pragma unroll
        for (int d = 0; d < 32; d++) {
            ull a[4];
            a[0] = *(const ull*)&As[d][ty8];
            a[1] = *(const ull*)&As[d][ty8 + 2];
            a[2] = *(const ull*)&As[d][ty8 + 4];
            a[3] = *(const ull*)&As[d][ty8 + 6];
            #pragma unroll
            for (int cc = 0; cc < 4; cc++) {
                ull bb;
                DUP2(bb, Ws[d][tx4 + cc]);
                FMA2(c[0][cc], a[0], bb, c[0][cc]);
                FMA2(c[1][cc], a[1], bb, c[1][cc]);
                FMA2(c[2][cc], a[2], bb, c[2][cc]);
                FMA2(c[3][cc], a[3], bb, c[3][cc]);
            }
        }
        __syncthreads();
    }
    #pragma unroll
    for (int j = 0; j < 4; j++) {
        int r0 = n0 + ty8 + 2 * j;
        #pragma unroll
        for (int cc = 0; cc < 4; cc++) {
            unsigned int lo, hi;
            asm("mov.b64 {%0, %1}, %2;" : "=r"(lo), "=r"(hi) : "l"(c[j][cc]));
            if (r0 < NN)
                out[(size_t)r0 * KHD + k * HH + tx4 + cc] = __uint_as_float(lo);
            if (r0 + 1 < NN)
                out[(size_t)(r0 + 1) * KHD + k * HH + tx4 + cc] = __uint_as_float(hi);
        }
    }
}

// ---------------- launch ----------------------------------------------------
// node_kernel sits at my launch index 3 -> IT is the profiled kernel.
extern "C" void kernel_launch(void* const* d_in, const int* in_sizes, int n_in,
                              void* d_out, int out_size) {
    const float* node_feat = (const float*)d_in[0]; // (N,128)
    const float* edge_feat = (const float*)d_in[1]; // (E,3,128)
    const float* W_enc     = (const float*)d_in[2]; // (128,512)
    const float* attn_l    = (const float*)d_in[3]; // (1,8,64)
    const float* W_r       = (const float*)d_in[4]; // (8,128)
    const int*   dst       = (const int*)d_in[5];   // (E,)
    float* out = (float*)d_out;                     // (N,8,64)

    er_count_kernel<<<(NN + 7) / 8, 256>>>(node_feat, W_r, dst, W_enc, attn_l); // 0
    scan_kernel<<<1, 1024>>>();                                                 // 1
    edge_kernel<<<EDGE_GRID, 128>>>((const float4*)edge_feat, dst);             // 2
    node_kernel<<<NN / 4, 128>>>();                                             // 3  <- profiled
    out_kernel<<<dim3((NN + 127) / 128, 8), 256>>>(W_enc, out);                 // 4
}